// round 15
// baseline (speedup 1.0000x reference)
#include <cuda_runtime.h>

// ADC module: out = x + alpha_c * sum_{3x3, zero-pad} |x - neighbor|
// x: (8, 64, 256, 256) fp32, alpha: (64,) fp32
//
// R14: R3's barrier-free immediate-consume structure, but lane owns 4 cols
// (one float4) instead of 8 -> 3-row window is 18 floats -> regs ~40 ->
// 48+ warps/SM instead of the register-capped 27 that limited every prior
// round. Warp = 32 rows x 128 cols; two warps split the image width; the
// warp-boundary column halo is fetched by lanes 0/31 as a scalar load
// (L2 hit -- sibling warp streams the same line).

#define IMG_H 256
#define IMG_W 256
#define STRIP_ROWS 32
#define N_IMG (8 * 64)
#define HALVES 2
#define STRIPS_PER_IMG (IMG_H / STRIP_ROWS)             // 8
#define WARPS_PER_IMG (STRIPS_PER_IMG * HALVES)         // 16
#define TOTAL_WARPS (N_IMG * WARPS_PER_IMG)             // 8192
#define BLOCK_THREADS 128
#define GRID_BLOCKS (TOTAL_WARPS * 32 / BLOCK_THREADS)  // 2048

struct Row {
    float v[4];
    float lh, rh;
};

__device__ __forceinline__ Row load_row(const float* __restrict__ img, int r,
                                        int col0, int lane) {
    Row row;
    bool valid = (r >= 0) && (r < IMG_H);   // r is warp-uniform
    if (valid) {
        float4 v = __ldcs(reinterpret_cast<const float4*>(img + (size_t)r * IMG_W + col0) + lane);
        row.v[0] = v.x; row.v[1] = v.y; row.v[2] = v.z; row.v[3] = v.w;
    } else {
        row.v[0] = row.v[1] = row.v[2] = row.v[3] = 0.0f;
    }
    float left  = __shfl_up_sync(0xffffffffu, row.v[3], 1);
    float right = __shfl_down_sync(0xffffffffu, row.v[0], 1);
    row.lh = left;
    row.rh = right;
    // Warp-edge halos: scalar fetch (L2-resident: the sibling warp streams it).
    if (lane == 0)
        row.lh = (valid && col0 > 0) ? __ldcs(img + (size_t)r * IMG_W + col0 - 1) : 0.0f;
    if (lane == 31)
        row.rh = (valid && col0 + 128 < IMG_W) ? __ldcs(img + (size_t)r * IMG_W + col0 + 128) : 0.0f;
    return row;
}

__global__ void __launch_bounds__(BLOCK_THREADS)
adc_kernel(const float* __restrict__ x, const float* __restrict__ alpha,
           float* __restrict__ out) {
    int gwarp = (blockIdx.x * BLOCK_THREADS + threadIdx.x) >> 5;
    int lane  = threadIdx.x & 31;

    int img   = gwarp / WARPS_PER_IMG;        // b*64 + c
    int rem   = gwarp - img * WARPS_PER_IMG;
    int strip = rem >> 1;
    int half  = rem & 1;
    int ch    = img & 63;
    float a   = __ldg(&alpha[ch]);

    const float* xi = x   + (size_t)img * IMG_H * IMG_W;
    float*       oi = out + (size_t)img * IMG_H * IMG_W;

    int r0   = strip * STRIP_ROWS;
    int col0 = half * 128;

    Row prev = load_row(xi, r0 - 1, col0, lane);
    Row cur  = load_row(xi, r0,     col0, lane);

#pragma unroll 4
    for (int r = r0; r < r0 + STRIP_ROWS; ++r) {
        Row next = load_row(xi, r + 1, col0, lane);

        float o[4];
#pragma unroll
        for (int j = 0; j < 4; ++j) {
            float c  = cur.v[j];
            float l  = (j == 0) ? cur.lh  : cur.v[j - 1];
            float rr = (j == 3) ? cur.rh  : cur.v[j + 1];
            float pl = (j == 0) ? prev.lh : prev.v[j - 1];
            float pc = prev.v[j];
            float pr = (j == 3) ? prev.rh : prev.v[j + 1];
            float nl = (j == 0) ? next.lh : next.v[j - 1];
            float nc = next.v[j];
            float nr = (j == 3) ? next.rh : next.v[j + 1];

            // center tap |c-c| == 0 for finite inputs -> skipped
            float s = fabsf(c - pl) + fabsf(c - pc) + fabsf(c - pr)
                    + fabsf(c - l)                  + fabsf(c - rr)
                    + fabsf(c - nl) + fabsf(c - nc) + fabsf(c - nr);
            o[j] = fmaf(a, s, c);
        }

        float4* po = reinterpret_cast<float4*>(oi + (size_t)r * IMG_W + col0) + lane;
        __stcs(po, make_float4(o[0], o[1], o[2], o[3]));

        prev = cur;
        cur  = next;
    }
}

extern "C" void kernel_launch(void* const* d_in, const int* in_sizes, int n_in,
                              void* d_out, int out_size) {
    const float* x     = (const float*)d_in[0];
    const float* alpha = (const float*)d_in[1];
    float*       out   = (float*)d_out;
    adc_kernel<<<GRID_BLOCKS, BLOCK_THREADS>>>(x, alpha, out);
}

// round 17
// speedup vs baseline: 1.0375x; 1.0375x over previous
#include <cuda_runtime.h>
#include <cstdint>

// ADC module: out = x + alpha_c * sum_{3x3, zero-pad} |x - neighbor|
// x: (8, 64, 256, 256) fp32, alpha: (64,) fp32
//
// R15: per-warp cp.async (LDGSTS) row ring. One warp per 32-row strip.
// Ring of 6 smem row slots; each slot = 272 floats: [3] and [260] are
// permanent zeros (the zero-pad columns), data in [4..259], 16B-aligned.
// Steady state per output row r: issue cp.async for row r+4 ->
// cp.async.wait_group 3 (rows <= r+1 complete) -> __syncwarp ->
// compute row r purely from smem (no shfl: halos are neighbor floats)
// -> 2x STG.128. 3KB/warp continuously in flight, zero register staging,
// zero block barriers.

#define IMG_H 256
#define IMG_W 256
#define STRIP_ROWS 32
#define N_IMG (8 * 64)
#define STRIPS_PER_IMG (IMG_H / STRIP_ROWS)   // 8
#define TOTAL_WARPS (N_IMG * STRIPS_PER_IMG)  // 4096
#define BLOCK_THREADS 128
#define WARPS_PER_BLOCK (BLOCK_THREADS / 32)  // 4
#define GRID_BLOCKS (TOTAL_WARPS / WARPS_PER_BLOCK)  // 1024

#define RING 6
#define ROWF 272            // floats per ring slot (1088 B; data at [4..259])

__device__ __forceinline__ void issue_row(uint32_t slot_addr,          // smem byte addr of slot float[0]
                                          const float* __restrict__ src_row,
                                          bool valid, int lane) {
    uint32_t d = slot_addr + 16 + lane * 32;   // float[4 + 8*lane]
    if (valid) {
        const float* s = src_row + lane * 8;
        asm volatile("cp.async.cg.shared.global [%0], [%1], 16;\n" :: "r"(d), "l"(s));
        asm volatile("cp.async.cg.shared.global [%0], [%1], 16;\n" :: "r"(d + 16), "l"(s + 4));
    } else {
        asm volatile("st.shared.v4.f32 [%0], {%1,%1,%1,%1};" :: "r"(d), "f"(0.0f));
        asm volatile("st.shared.v4.f32 [%0], {%1,%1,%1,%1};" :: "r"(d + 16), "f"(0.0f));
    }
    // One group per row per thread (empty group for invalid rows keeps
    // the wait_group bookkeeping uniform).
    asm volatile("cp.async.commit_group;");
}

__global__ void __launch_bounds__(BLOCK_THREADS)
adc_kernel(const float* __restrict__ x, const float* __restrict__ alpha,
           float* __restrict__ out) {
    __shared__ float ring[WARPS_PER_BLOCK][RING][ROWF];   // 4*6*272*4 = 26112 B

    int t     = threadIdx.x;
    int w     = t >> 5;
    int lane  = t & 31;
    int gwarp = blockIdx.x * WARPS_PER_BLOCK + w;

    int img   = gwarp >> 3;                   // b*64 + c
    int strip = gwarp & 7;
    int ch    = img & 63;
    float a   = __ldg(&alpha[ch]);

    const float* xi = x   + (size_t)img * IMG_H * IMG_W;
    float*       oi = out + (size_t)img * IMG_H * IMG_W;

    int r0  = strip * STRIP_ROWS;
    int rlo = (r0 == 0) ? 0 : r0 - 1;
    int rhi = (r0 + STRIP_ROWS > IMG_H - 1) ? IMG_H - 1 : r0 + STRIP_ROWS;

    float (*wr)[ROWF] = ring[w];
    uint32_t wbase = (uint32_t)__cvta_generic_to_shared(&wr[0][0]);

    // Permanent zero-pad columns for all slots.
    if (lane < RING) {
        wr[lane][3]   = 0.0f;
        wr[lane][260] = 0.0f;
    }
    __syncwarp();

    // Prologue: rows r0-1 .. r0+3 into slots 0..4.
#pragma unroll
    for (int k = 0; k < 5; ++k) {
        int rr = r0 - 1 + k;
        issue_row(wbase + (uint32_t)(k * ROWF * 4), xi + (size_t)rr * IMG_W,
                  rr >= rlo && rr <= rhi, lane);
    }

    int sp = 0, sc = 1, sn = 2, si = 5;       // slots of rows r-1, r, r+1, r+4

#pragma unroll 2
    for (int r = r0; r < r0 + STRIP_ROWS; ++r) {
        // Issue row r+4 into the slot vacated by row r-2.
        int rr = r + 4;
        issue_row(wbase + (uint32_t)(si * ROWF * 4), xi + (size_t)rr * IMG_W,
                  rr >= rlo && rr <= rhi, lane);

        // Rows <= r+1 are complete once at most 3 groups (r+2..r+4) pend.
        asm volatile("cp.async.wait_group 3;");
        __syncwarp();

        const float* rp = &wr[sp][4 + lane * 8];
        const float* rc = &wr[sc][4 + lane * 8];
        const float* rn = &wr[sn][4 + lane * 8];

        float p[8], c[8], n[8];
        {
            float4 a0 = *reinterpret_cast<const float4*>(rp);
            float4 a1 = *reinterpret_cast<const float4*>(rp + 4);
            p[0]=a0.x; p[1]=a0.y; p[2]=a0.z; p[3]=a0.w;
            p[4]=a1.x; p[5]=a1.y; p[6]=a1.z; p[7]=a1.w;
            float4 b0 = *reinterpret_cast<const float4*>(rc);
            float4 b1 = *reinterpret_cast<const float4*>(rc + 4);
            c[0]=b0.x; c[1]=b0.y; c[2]=b0.z; c[3]=b0.w;
            c[4]=b1.x; c[5]=b1.y; c[6]=b1.z; c[7]=b1.w;
            float4 c0 = *reinterpret_cast<const float4*>(rn);
            float4 c1 = *reinterpret_cast<const float4*>(rn + 4);
            n[0]=c0.x; n[1]=c0.y; n[2]=c0.z; n[3]=c0.w;
            n[4]=c1.x; n[5]=c1.y; n[6]=c1.z; n[7]=c1.w;
        }
        float plh = rp[-1], prh = rp[8];
        float clh = rc[-1], crh = rc[8];
        float nlh = rn[-1], nrh = rn[8];

        float o[8];
#pragma unroll
        for (int j = 0; j < 8; ++j) {
            float cc = c[j];
            float pl = (j == 0) ? plh : p[j - 1];
            float pr = (j == 7) ? prh : p[j + 1];
            float l  = (j == 0) ? clh : c[j - 1];
            float rr2= (j == 7) ? crh : c[j + 1];
            float nl = (j == 0) ? nlh : n[j - 1];
            float nr = (j == 7) ? nrh : n[j + 1];

            // center tap |c-c| == 0 for finite inputs -> skipped
            float s = fabsf(cc - pl) + fabsf(cc - p[j]) + fabsf(cc - pr)
                    + fabsf(cc - l)                     + fabsf(cc - rr2)
                    + fabsf(cc - nl) + fabsf(cc - n[j]) + fabsf(cc - nr);
            o[j] = fmaf(a, s, cc);
        }

        float4* po = reinterpret_cast<float4*>(oi + (size_t)r * IMG_W + lane * 8);
        __stcs(po,     make_float4(o[0], o[1], o[2], o[3]));
        __stcs(po + 1, make_float4(o[4], o[5], o[6], o[7]));

        // Rotate slot indices (cheap scalar ints, not Row structs).
        sp = sc; sc = sn;
        sn = (sn + 1 == RING) ? 0 : sn + 1;
        si = (si + 1 == RING) ? 0 : si + 1;
    }
}

extern "C" void kernel_launch(void* const* d_in, const int* in_sizes, int n_in,
                              void* d_out, int out_size) {
    const float* x     = (const float*)d_in[0];
    const float* alpha = (const float*)d_in[1];
    float*       out   = (float*)d_out;
    adc_kernel<<<GRID_BLOCKS, BLOCK_THREADS>>>(x, alpha, out);
}